// round 17
// baseline (speedup 1.0000x reference)
#include <cuda_runtime.h>
#include <math.h>

#define BB 16
#define HH 512
#define WW 512
#define NTOT (BB * HH * WW)

#define RAD 10
#define NROWS (BB * HH)    // 8192
#define NB1 1024           // K1 blocks
#define NB2 1024           // K2 blocks
#define SENTW 0x64646464u  // four u8 bytes of 100

// Scratch (no allocation allowed in kernel_launch)
__device__ unsigned char g_f2[NTOT];     // horizontal distance^2 (<=100), u8
__device__ unsigned short g_p16[NTOT];   // p = sigmoid(x), u16 fixed-point
__device__ unsigned char g_acb[NROWS];   // per-row activity (any fg in row)
__device__ float g_pf[NB1];              // K1: exact focal partials
__device__ float g_pl[NB1];              // K1: base loss partials
__device__ float g_pc[NB2];              // K2: correction partials
__device__ unsigned g_done = 0;          // last-block counter (self-resets)

// ---------------------------------------------------------------------------
// K1: one WARP per image row, dual stream (inp+tgt read ONCE, never again).
//  - fg mask bits -> f^2-u8 via shfl/clz/ffs (clamped 10; rides idle slots)
//  - p = sigmoid(x); EXACT fsum = a*s^2; BASE lsum = a*s^4
//    (bg: h=0 assumed -> 0.15 p^4; fg: h=1 exact -> 0.85 q^4)
//  - stores f^2 (16B/lane), p-u16 (32B/lane, err 7.6e-6), activity byte
//  - warp+block reduce -> g_pf/g_pl partials
// ---------------------------------------------------------------------------
__global__ __launch_bounds__(256) void k1_base(const float* __restrict__ inp,
                                               const float* __restrict__ tgt) {
    const int tid = threadIdx.x;
    const int gid = blockIdx.x * 256 + tid;
    const int row = gid >> 5;
    const int lane = gid & 31;
    const size_t base = (size_t)row * WW + lane * 16;

    const float4* tp = (const float4*)(tgt + base);
    const float4* xp = (const float4*)(inp + base);
    float4 t0 = tp[0], t1 = tp[1], t2 = tp[2], t3 = tp[3];
    float4 x0 = xp[0], x1 = xp[1], x2 = xp[2], x3 = xp[3];

    unsigned m = 0;
    m |= (t0.x > 0.5f) ? 1u << 0 : 0u;
    m |= (t0.y > 0.5f) ? 1u << 1 : 0u;
    m |= (t0.z > 0.5f) ? 1u << 2 : 0u;
    m |= (t0.w > 0.5f) ? 1u << 3 : 0u;
    m |= (t1.x > 0.5f) ? 1u << 4 : 0u;
    m |= (t1.y > 0.5f) ? 1u << 5 : 0u;
    m |= (t1.z > 0.5f) ? 1u << 6 : 0u;
    m |= (t1.w > 0.5f) ? 1u << 7 : 0u;
    m |= (t2.x > 0.5f) ? 1u << 8 : 0u;
    m |= (t2.y > 0.5f) ? 1u << 9 : 0u;
    m |= (t2.z > 0.5f) ? 1u << 10 : 0u;
    m |= (t2.w > 0.5f) ? 1u << 11 : 0u;
    m |= (t3.x > 0.5f) ? 1u << 12 : 0u;
    m |= (t3.y > 0.5f) ? 1u << 13 : 0u;
    m |= (t3.z > 0.5f) ? 1u << 14 : 0u;
    m |= (t3.w > 0.5f) ? 1u << 15 : 0u;

    unsigned anyb = __ballot_sync(0xffffffffu, m != 0u);
    unsigned left = __shfl_up_sync(0xffffffffu, m, 1);
    unsigned right = __shfl_down_sync(0xffffffffu, m, 1);
    if (lane == 0) left = 0;
    if (lane == 31) right = 0;
    unsigned long long w = (unsigned long long)left |
                           ((unsigned long long)m << 16) |
                           ((unsigned long long)right << 32);

    // f^2 u8 words
    unsigned ow[4];
#pragma unroll
    for (int k = 0; k < 4; k++) {
        unsigned bw = 0;
#pragma unroll
        for (int u = 0; u < 4; u++) {
            int pcol = 4 * k + u;
            unsigned win = (unsigned)(w >> (pcol + 6)) & 0x1FFFFFu;
            unsigned wl = win & 0x7FFu;
            int dl = __clz(wl) - 21;
            unsigned wr = (win >> 10) | 0x800u;
            int dr = __ffs((int)wr) - 1;
            int f = min(min(dl, dr), 10);
            bw |= (unsigned)(f * f) << (8 * u);
        }
        ow[k] = bw;
    }
    *(uint4*)(g_f2 + base) = make_uint4(ow[0], ow[1], ow[2], ow[3]);
    if (lane == 0) g_acb[row] = (anyb != 0u) ? 1 : 0;

    // sigmoid + focal (exact) + base loss; pack p-u16
    float fs = 0.0f, ls = 0.0f;
    unsigned short pk[16];
#define PX(xv, bit)                                       \
    {                                                     \
        bool pos = (m >> (bit)) & 1u;                     \
        float p = __fdividef(1.0f, 1.0f + __expf(-(xv))); \
        pk[bit] = (unsigned short)(p * 65535.0f + 0.5f);  \
        float s = pos ? (1.0f - p) : p;                   \
        float a = pos ? 0.85f : 0.15f;                    \
        float s2 = s * s;                                 \
        float f = a * s2;                                 \
        fs += f;                                          \
        ls = fmaf(f, s2, ls);                             \
    }
    PX(x0.x, 0) PX(x0.y, 1) PX(x0.z, 2) PX(x0.w, 3)
    PX(x1.x, 4) PX(x1.y, 5) PX(x1.z, 6) PX(x1.w, 7)
    PX(x2.x, 8) PX(x2.y, 9) PX(x2.z, 10) PX(x2.w, 11)
    PX(x3.x, 12) PX(x3.y, 13) PX(x3.z, 14) PX(x3.w, 15)
#undef PX
    *(uint4*)(g_p16 + base) = *(uint4*)&pk[0];
    *(uint4*)(g_p16 + base + 8) = *(uint4*)&pk[8];

    __shared__ float swF[8], swL[8];
#pragma unroll
    for (int off = 16; off > 0; off >>= 1) {
        fs += __shfl_xor_sync(0xffffffffu, fs, off);
        ls += __shfl_xor_sync(0xffffffffu, ls, off);
    }
    if (lane == 0) {
        swF[tid >> 5] = fs;
        swL[tid >> 5] = ls;
    }
    __syncthreads();
    if (tid == 0) {
        float F = 0.0f, Lv = 0.0f;
#pragma unroll
        for (int ww = 0; ww < 8; ww++) {
            F += swF[ww];
            Lv += swL[ww];
        }
        g_pf[blockIdx.x] = F;
        g_pl[blockIdx.x] = Lv;
    }
}

// ---------------------------------------------------------------------------
// K2: correction only — touches NO DRAM stream (g_f2/g_p16/g_acb are fresh
// in L2). One warp per row. SIMD taps (activity-gated); then per-lane byte
// masks select pixels with 0 < dmin < 100 (~4/lane) and add
//   dl = 0.15 * p^2 * h * (h - 2p),  h = exp(-dmin/8), p from u16.
// fg px (dmin==0: base exact) and far px (dmin==100: h~0) need nothing.
// ---------------------------------------------------------------------------
__global__ __launch_bounds__(256) void k2_corr(float* __restrict__ out) {
    const int tid = threadIdx.x;
    const int lane = tid & 31;
    const int wid = tid >> 5;
    const int gr = blockIdx.x * 8 + wid;  // global row
    const int b = gr >> 9;
    const int i = gr & 511;

    __shared__ float swC[8];
    __shared__ int slast;
    __shared__ double sred[512];

    // activity ballot over rows i-10..i+10
    int r = i - RAD + lane;
    unsigned char ab = 0;
    if (lane < 2 * RAD + 1 && (unsigned)r < HH) ab = g_acb[(b << 9) + r];
    unsigned rm = __ballot_sync(0xffffffffu, ab != 0) & 0x1FFFFFu;

    float csum = 0.0f;
    if (rm) {
        uint4 acc = make_uint4(SENTW, SENTW, SENTW, SENTW);
        const unsigned char* fb =
            g_f2 + ((size_t)(b << 9) + (i - RAD)) * WW + lane * 16;
        while (rm) {
            int t = __ffs(rm) - 1;
            rm &= rm - 1;
            uint4 v = *(const uint4*)(fb + (size_t)t * WW);
            int dm = t - RAD;
            unsigned wb = (unsigned)(dm * dm) * 0x01010101u;
            acc.x = __vminu4(acc.x, __vaddus4(v.x, wb));
            acc.y = __vminu4(acc.y, __vaddus4(v.y, wb));
            acc.z = __vminu4(acc.z, __vaddus4(v.z, wb));
            acc.w = __vminu4(acc.w, __vaddus4(v.w, wb));
        }
        const unsigned short* prow = g_p16 + (size_t)gr * WW + lane * 16;
        unsigned aw[4] = {acc.x, acc.y, acc.z, acc.w};
#pragma unroll
        for (int k = 0; k < 4; k++) {
            unsigned accw = aw[k];
            unsigned mw = __vcmpltu4(accw, SENTW) & __vcmpgtu4(accw, 0u);
            while (mw) {
                int bp = (__ffs(mw) - 1) & ~7;  // byte start bit
                mw &= ~(0xFFu << bp);
                int d = (accw >> bp) & 255;
                float p = (float)prow[4 * k + (bp >> 3)] * (1.0f / 65535.0f);
                float h = __expf((float)d * -0.125f);
                csum = fmaf(p * p * h, h - 2.0f * p, csum);
            }
        }
        csum *= 0.15f;
    }

    // reduce
#pragma unroll
    for (int off = 16; off > 0; off >>= 1)
        csum += __shfl_xor_sync(0xffffffffu, csum, off);
    if (lane == 0) swC[wid] = csum;
    __syncthreads();

    if (tid == 0) {
        float C = 0.0f;
#pragma unroll
        for (int ww = 0; ww < 8; ww++) C += swC[ww];
        g_pc[blockIdx.x] = C;
        __threadfence();
        unsigned old = atomicAdd(&g_done, 1u);
        slast = (old == NB2 - 1) ? 1 : 0;
    }
    __syncthreads();

    // last block: fold final scalar
    if (slast) {
        __threadfence();
        double* sFd = sred;
        double* sLd = sred + 256;
        double f = 0.0, l = 0.0;
        for (int k = tid; k < NB1; k += 256) {
            f += (double)g_pf[k];
            l += (double)g_pl[k];
        }
        for (int k = tid; k < NB2; k += 256) l += (double)g_pc[k];
        sFd[tid] = f;
        sLd[tid] = l;
        __syncthreads();
#pragma unroll
        for (int s = 128; s > 0; s >>= 1) {
            if (tid < s) {
                sFd[tid] += sFd[tid + s];
                sLd[tid] += sLd[tid + s];
            }
            __syncthreads();
        }
        if (tid == 0) {
            double n = (double)NTOT;
            double denom = sFd[0] / n + 0.01;
            out[0] = (float)(2.0 * (sLd[0] / n) / denom);
            g_done = 0;  // reset for next graph replay
        }
    }
}

extern "C" void kernel_launch(void* const* d_in, const int* in_sizes, int n_in,
                              void* d_out, int out_size) {
    const float* inp = (const float*)d_in[0];
    const float* tgt = (const float*)d_in[1];
    float* out = (float*)d_out;

    k1_base<<<NB1, 256>>>(inp, tgt);
    k2_corr<<<NB2, 256>>>(out);
}